// round 12
// baseline (speedup 1.0000x reference)
#include <cuda_runtime.h>

// Occupancy connectivity loss over a 385^3 fp32 grid, C order:
//   f = x*385^2 + y*385 + z
// Warp-autonomous: NO block barriers, NO smem data exchange.
// Each warp owns a 5(y) x 31(z) tile and marches 48 planes in x:
//   rows 0..4 owned, row 5 = y-halo (registers)
//   lanes: z = zb + lane, zb = 31*ztile (tiles overlap by 1 column)
//   y-diff: in-register between adjacent row registers
//   z-diff: shfl_down(row, 1), lanes 0..30 accumulate
//   x-diff: vs prefetched next plane's registers
// Boundary handling via clamped duplicate loads (diff contributes exact 0).
// Small tiles -> 1001 blocks -> ~6.8 blocks/SM in one wave (high occupancy).

#define ROW    385u
#define PLANE  148225u
#define NZT    13u                 // z tiles: zb = 0,31,...,372
#define NYG    77u                 // y groups of 5 owned rows (5*77 = 385)
#define XC     8u                  // x chunks of 48 planes
#define WPB    8u
#define NTASKS (NZT * NYG * XC)    // 8008 warp tasks
#define NBLOCKS (NTASKS / WPB)     // 1001

__device__ double   g_part[NBLOCKS];
__device__ unsigned g_count = 0;

__global__ void __launch_bounds__(256, 7)
occ_main(const float* __restrict__ occ, float* __restrict__ out) {
    const unsigned wid  = threadIdx.x >> 5;
    const unsigned lane = threadIdx.x & 31u;

    const unsigned w  = blockIdx.x * WPB + wid;
    const unsigned zt = w % NZT;
    const unsigned r1 = w / NZT;
    const unsigned yg = r1 % NYG;
    const unsigned xc = r1 / NYG;

    const unsigned zb = zt * 31u;
    const unsigned z  = min(zb + lane, 384u);       // clamp: dup loads harmless
    const unsigned yb = yg * 5u;

    const bool lastzt = (zt == NZT - 1u);
    const bool yxm = lane < (lastzt ? 13u : 31u);   // owned z columns
    const bool zm  = lane < (lastzt ? 12u : 31u);   // owned z pairs

    const bool lastc = (xc == XC - 1u);
    // last y group: halo row duplicates y=384 -> y-diff contributes 0
    const unsigned off5 = (yg == NYG - 1u) ? 4u * ROW : 5u * ROW;

    const float* p = occ + (size_t)yb * ROW + z + (size_t)(48u * xc) * PLANE;

    float s0 = 0.f, s1 = 0.f;
    float v[6], n[6];

    v[0]=__ldg(p);        v[1]=__ldg(p+ROW);    v[2]=__ldg(p+2u*ROW);
    v[3]=__ldg(p+3u*ROW); v[4]=__ldg(p+4u*ROW); v[5]=__ldg(p+off5);

    #define LOAD(A) do { p += PLANE;                                        \
        A[0]=__ldg(p);        A[1]=__ldg(p+ROW);    A[2]=__ldg(p+2u*ROW);   \
        A[3]=__ldg(p+3u*ROW); A[4]=__ldg(p+4u*ROW); A[5]=__ldg(p+off5);     \
        } while(0)

    // diffs for the plane held in V; N = next plane (x-diff partner)
    #define BODY(V,N) do {                                                  \
        _Pragma("unroll")                                                   \
        for (int r = 0; r < 5; ++r) {                                       \
            float zn = __shfl_down_sync(0xffffffffu, V[r], 1);              \
            float dz = fabsf(zn - V[r]);                                    \
            float dy = fabsf(V[r+1] - V[r]);                                \
            float dx = fabsf(N[r]   - V[r]);                                \
            if (zm)  s0 += dz;                                              \
            if (yxm) { s0 += dy; s1 += dx; }                                \
        } } while(0)

    // 48 x-pairs per chunk; unrolled x2 with register-role swap (no moves)
    #pragma unroll 1
    for (int i = 0; i < 48; i += 2) {
        LOAD(n);
        BODY(v, n);
        LOAD(v);
        BODY(n, v);
    }

    // final plane x = 384 (last chunk only): z/y diffs, no x-diff
    if (lastc) {
        #pragma unroll
        for (int r = 0; r < 5; ++r) {
            float zn = __shfl_down_sync(0xffffffffu, v[r], 1);
            float dz = fabsf(zn - v[r]);
            float dy = fabsf(v[r+1] - v[r]);
            if (zm)  s0 += dz;
            if (yxm) s0 += dy;
        }
    }

    // ---- block reduction ----
    float s = s0 + s1;
    #pragma unroll
    for (int o = 16; o > 0; o >>= 1)
        s += __shfl_down_sync(0xffffffffu, s, o);

    __shared__ float    ws[WPB];
    __shared__ unsigned islast_s;
    if (lane == 0u) ws[wid] = s;
    __syncthreads();
    if (threadIdx.x == 0u) {
        float t = 0.f;
        #pragma unroll
        for (unsigned i = 0; i < WPB; ++i) t += ws[i];
        g_part[blockIdx.x] = (double)t;
        __threadfence();
        unsigned old = atomicAdd(&g_count, 1u);
        islast_s = (old == NBLOCKS - 1u) ? 1u : 0u;
    }
    __syncthreads();

    // ---- last block folds partials (single launch total) ----
    if (islast_s) {
        double d = 0.0;
        for (unsigned i = threadIdx.x; i < NBLOCKS; i += 256u)
            d += g_part[i];
        __shared__ double dsm[256];
        dsm[threadIdx.x] = d;
        __syncthreads();
        #pragma unroll
        for (int st = 128; st > 0; st >>= 1) {
            if ((int)threadIdx.x < st) dsm[threadIdx.x] += dsm[threadIdx.x + st];
            __syncthreads();
        }
        if (threadIdx.x == 0u) {
            out[0] = (float)dsm[0];
            g_count = 0u;   // reset for next graph replay
        }
    }
}

extern "C" void kernel_launch(void* const* d_in, const int* in_sizes, int n_in,
                              void* d_out, int out_size) {
    const float* occ = (const float*)d_in[0];
    float* out = (float*)d_out;
    occ_main<<<NBLOCKS, 256>>>(occ, out);
}